// round 13
// baseline (speedup 1.0000x reference)
#include <cuda_runtime.h>

// out_i = sign(x) * u_i / ||u||, u = W[0,1:4]; 0 when x == 0.
// R2's winning shape (single wave, 1024 CTAs x 256 thr, block-contiguous
// chunks, front-batched float4 loads) with stores reordered PLANE-MAJOR:
// each CTA emits all its plane-0 stores (16KB contiguous), then plane-1,
// then plane-2, improving write-stream locality at L2/DRAM.

#define HWPIX (512 * 512)            // 2^18 elements per plane
#define NBATCH 16
#define F4_PER_THREAD 4
#define THREADS 256
#define BLOCK_ELEMS (THREADS * F4_PER_THREAD * 4)   // 4096 elems per block

__global__ __launch_bounds__(THREADS) void scene_normal_kernel(
    const float4* __restrict__ depth4,   // [16*512*512/4]
    const float*  __restrict__ Wm,       // [8,8] row-major
    float* __restrict__ out)             // [16,3,512,512] flat
{
    const float u1 = Wm[1];
    const float u2 = Wm[2];
    const float u3 = Wm[3];
    const float r  = rsqrtf(u1 * u1 + u2 * u2 + u3 * u3);
    const float c1 = u1 * r, c2 = u2 * r, c3 = u3 * r;

    const int n0   = blockIdx.x * BLOCK_ELEMS;   // block-contiguous chunk
    const int b    = n0 >> 18;                   // HWPIX | BLOCK_ELEMS*64
    const int rem0 = n0 & (HWPIX - 1);

    const float4* in4 = depth4 + (n0 >> 2) + threadIdx.x;
    float* basep = out + (size_t)b * 3 * HWPIX + rem0;
    float4* o1 = reinterpret_cast<float4*>(basep) + threadIdx.x;
    float4* o2 = reinterpret_cast<float4*>(basep + HWPIX) + threadIdx.x;
    float4* o3 = reinterpret_cast<float4*>(basep + 2 * HWPIX) + threadIdx.x;

    // Front-batch all loads (MLP = 4), compute signs once.
    float4 x[F4_PER_THREAD];
#pragma unroll
    for (int i = 0; i < F4_PER_THREAD; i++)
        x[i] = in4[i * THREADS];

    float4 s[F4_PER_THREAD];
#pragma unroll
    for (int i = 0; i < F4_PER_THREAD; i++) {
        s[i].x = (x[i].x > 0.f) ? 1.f : ((x[i].x < 0.f) ? -1.f : 0.f);
        s[i].y = (x[i].y > 0.f) ? 1.f : ((x[i].y < 0.f) ? -1.f : 0.f);
        s[i].z = (x[i].z > 0.f) ? 1.f : ((x[i].z < 0.f) ? -1.f : 0.f);
        s[i].w = (x[i].w > 0.f) ? 1.f : ((x[i].w < 0.f) ? -1.f : 0.f);
    }

    // Plane-major store order: 16KB contiguous per plane per CTA.
#pragma unroll
    for (int i = 0; i < F4_PER_THREAD; i++)
        o1[i * THREADS] = make_float4(s[i].x * c1, s[i].y * c1, s[i].z * c1, s[i].w * c1);
#pragma unroll
    for (int i = 0; i < F4_PER_THREAD; i++)
        o2[i * THREADS] = make_float4(s[i].x * c2, s[i].y * c2, s[i].z * c2, s[i].w * c2);
#pragma unroll
    for (int i = 0; i < F4_PER_THREAD; i++)
        o3[i * THREADS] = make_float4(s[i].x * c3, s[i].y * c3, s[i].z * c3, s[i].w * c3);
}

extern "C" void kernel_launch(void* const* d_in, const int* in_sizes, int n_in,
                              void* d_out, int out_size)
{
    const float4* depth4 = (const float4*)d_in[0];
    const float*  Wm     = (const float*)d_in[1];
    float* out           = (float*)d_out;

    const int n_elems = NBATCH * HWPIX;          // 4,194,304
    const int blocks  = n_elems / BLOCK_ELEMS;   // 1024 (single wave)

    scene_normal_kernel<<<blocks, THREADS>>>(depth4, Wm, out);
}